// round 1
// baseline (speedup 1.0000x reference)
#include <cuda_runtime.h>
#include <math.h>

#define B_   4
#define S_   2048
#define EMB_ 1024
#define H_   16
#define HD_  64
#define M_   (B_ * S_)   // 8192

// ---------------- scratch (device globals; no allocation allowed) ----------
__device__ float g_q[(size_t)B_ * H_ * S_ * HD_];
__device__ float g_k[(size_t)B_ * H_ * S_ * HD_];
__device__ float g_v[(size_t)B_ * H_ * S_ * HD_];
__device__ float g_attn[(size_t)M_ * EMB_];

// ---------------- GEMM: Y = A @ W^T  (A:[M,K] row-major, W:[N,K] row-major) -
constexpr int BM = 128, BN = 128, BK = 8;

__device__ __forceinline__ void gemm_core(const float* __restrict__ A,
                                          const float* __restrict__ W,
                                          float acc[8][8],
                                          int row0, int col0, int Kdim)
{
    __shared__ float As[BK][BM + 4];
    __shared__ float Bs[BK][BN + 4];

    const int t  = threadIdx.x;
    const int lr = t >> 1;            // 0..127 (tile row for loads)
    const int lc = (t & 1) * 4;       // 0 or 4 (k-offset for loads)
    const int ty = t >> 4;            // 0..15
    const int tx = t & 15;            // 0..15

    const float* aptr = A + (size_t)(row0 + lr) * Kdim + lc;
    const float* wptr = W + (size_t)(col0 + lr) * Kdim + lc;

    for (int kb = 0; kb < Kdim; kb += BK) {
        float4 av = *(const float4*)(aptr + kb);
        float4 wv = *(const float4*)(wptr + kb);
        As[lc + 0][lr] = av.x; As[lc + 1][lr] = av.y;
        As[lc + 2][lr] = av.z; As[lc + 3][lr] = av.w;
        Bs[lc + 0][lr] = wv.x; Bs[lc + 1][lr] = wv.y;
        Bs[lc + 2][lr] = wv.z; Bs[lc + 3][lr] = wv.w;
        __syncthreads();

        #pragma unroll
        for (int k = 0; k < BK; ++k) {
            float a[8], b[8];
            *(float4*)(a)     = *(const float4*)&As[k][ty * 8];
            *(float4*)(a + 4) = *(const float4*)&As[k][ty * 8 + 4];
            *(float4*)(b)     = *(const float4*)&Bs[k][tx * 8];
            *(float4*)(b + 4) = *(const float4*)&Bs[k][tx * 8 + 4];
            #pragma unroll
            for (int i = 0; i < 8; ++i)
                #pragma unroll
                for (int j = 0; j < 8; ++j)
                    acc[i][j] = fmaf(a[i], b[j], acc[i][j]);
        }
        __syncthreads();
    }
}

// QKV projection: blockIdx.z selects {Q,K,V}; epilogue scatters to [B,H,S,hd]
__global__ __launch_bounds__(256) void qkv_kernel(
    const float* __restrict__ x,
    const float* __restrict__ Wq, const float* __restrict__ bq,
    const float* __restrict__ Wk, const float* __restrict__ bk,
    const float* __restrict__ Wv, const float* __restrict__ bv)
{
    const float* W;  const float* bias;  float* out;
    if (blockIdx.z == 0)      { W = Wq; bias = bq; out = g_q; }
    else if (blockIdx.z == 1) { W = Wk; bias = bk; out = g_k; }
    else                      { W = Wv; bias = bv; out = g_v; }

    const int row0 = blockIdx.y * BM;
    const int col0 = blockIdx.x * BN;

    float acc[8][8] = {};
    gemm_core(x, W, acc, row0, col0, EMB_);

    const int ty = threadIdx.x >> 4, tx = threadIdx.x & 15;
    #pragma unroll
    for (int i = 0; i < 8; ++i) {
        int m  = row0 + ty * 8 + i;
        int bb = m / S_;
        int s  = m % S_;
        #pragma unroll
        for (int j0 = 0; j0 < 8; j0 += 4) {
            int n = col0 + tx * 8 + j0;
            int h = n >> 6, d = n & 63;
            float4 v;
            v.x = acc[i][j0 + 0] + bias[n + 0];
            v.y = acc[i][j0 + 1] + bias[n + 1];
            v.z = acc[i][j0 + 2] + bias[n + 2];
            v.w = acc[i][j0 + 3] + bias[n + 3];
            *(float4*)&out[(((size_t)bb * H_ + h) * S_ + s) * HD_ + d] = v;
        }
    }
}

// Output projection: d_out = g_attn @ Wo^T + bo
__global__ __launch_bounds__(256) void oproj_kernel(
    const float* __restrict__ Wo, const float* __restrict__ bo,
    float* __restrict__ out)
{
    const int row0 = blockIdx.y * BM;
    const int col0 = blockIdx.x * BN;

    float acc[8][8] = {};
    gemm_core(g_attn, Wo, acc, row0, col0, EMB_);

    const int ty = threadIdx.x >> 4, tx = threadIdx.x & 15;
    #pragma unroll
    for (int i = 0; i < 8; ++i) {
        int m = row0 + ty * 8 + i;
        #pragma unroll
        for (int j0 = 0; j0 < 8; j0 += 4) {
            int n = col0 + tx * 8 + j0;
            float4 v;
            v.x = acc[i][j0 + 0] + bo[n + 0];
            v.y = acc[i][j0 + 1] + bo[n + 1];
            v.z = acc[i][j0 + 2] + bo[n + 2];
            v.w = acc[i][j0 + 3] + bo[n + 3];
            *(float4*)&out[(size_t)m * EMB_ + n] = v;
        }
    }
}

// ---------------- causal flash attention (fp32, online softmax) -----------
constexpr int AT   = 64;    // q/k tile
constexpr int APAD = 68;    // padded row stride (floats)
constexpr int ATTN_SMEM = 4 * AT * APAD * (int)sizeof(float);  // 69632 B

__global__ __launch_bounds__(256) void attn_kernel()
{
    extern __shared__ float sm[];
    float (*Qs)[APAD] = (float(*)[APAD])(sm);
    float (*Kt)[APAD] = (float(*)[APAD])(sm + 1 * AT * APAD);  // transposed: Kt[d][k]
    float (*Vs)[APAD] = (float(*)[APAD])(sm + 2 * AT * APAD);
    float (*Ps)[APAD] = (float(*)[APAD])(sm + 3 * AT * APAD);

    const int qt = blockIdx.x;          // q tile index (0..31)
    const int bh = blockIdx.y;          // b*H + h     (0..63)
    const float* Qg = g_q + (size_t)bh * S_ * HD_;
    const float* Kg = g_k + (size_t)bh * S_ * HD_;
    const float* Vg = g_v + (size_t)bh * S_ * HD_;

    const int t  = threadIdx.x;
    const int tx = t & 15;              // col group (k cols / head dims)
    const int ty = t >> 4;              // row group (q rows)

    // Load Q tile once (64x64 floats)
    #pragma unroll
    for (int r = 0; r < 4; ++r) {
        int id  = t + r * 256;
        int row = id >> 4;
        int c4  = (id & 15) * 4;
        *(float4*)&Qs[row][c4] =
            *(const float4*)&Qg[(size_t)(qt * AT + row) * HD_ + c4];
    }

    float m[4], l[4], acc[4][4];
    #pragma unroll
    for (int i = 0; i < 4; ++i) {
        m[i] = -1e30f; l[i] = 0.0f;
        #pragma unroll
        for (int j = 0; j < 4; ++j) acc[i][j] = 0.0f;
    }
    const float scale = 0.125f;  // 1/sqrt(64)

    for (int kt = 0; kt <= qt; ++kt) {
        __syncthreads();  // previous PV reads (and Q load on iter 0) done

        // Load K tile transposed + V tile
        #pragma unroll
        for (int r = 0; r < 4; ++r) {
            int id  = t + r * 256;
            int row = id >> 4;
            int c4  = (id & 15) * 4;
            float4 kv = *(const float4*)&Kg[(size_t)(kt * AT + row) * HD_ + c4];
            Kt[c4 + 0][row] = kv.x; Kt[c4 + 1][row] = kv.y;
            Kt[c4 + 2][row] = kv.z; Kt[c4 + 3][row] = kv.w;
            *(float4*)&Vs[row][c4] =
                *(const float4*)&Vg[(size_t)(kt * AT + row) * HD_ + c4];
        }
        __syncthreads();

        // S = (Q K^T) * scale
        float s[4][4] = {};
        #pragma unroll
        for (int d4 = 0; d4 < 16; ++d4) {
            float4 q4[4];
            #pragma unroll
            for (int i = 0; i < 4; ++i)
                q4[i] = *(const float4*)&Qs[ty * 4 + i][d4 * 4];
            #pragma unroll
            for (int dd = 0; dd < 4; ++dd) {
                float4 k4 = *(const float4*)&Kt[d4 * 4 + dd][tx * 4];
                #pragma unroll
                for (int i = 0; i < 4; ++i) {
                    float qv = ((const float*)&q4[i])[dd];
                    s[i][0] = fmaf(qv, k4.x, s[i][0]);
                    s[i][1] = fmaf(qv, k4.y, s[i][1]);
                    s[i][2] = fmaf(qv, k4.z, s[i][2]);
                    s[i][3] = fmaf(qv, k4.w, s[i][3]);
                }
            }
        }

        const bool diag = (kt == qt);
        #pragma unroll
        for (int i = 0; i < 4; ++i) {
            int li = ty * 4 + i;  // local q row
            #pragma unroll
            for (int j = 0; j < 4; ++j) {
                float v = s[i][j] * scale;
                if (diag && (tx * 4 + j) > li) v = -1e30f;
                s[i][j] = v;
            }
        }

        // Online softmax (row groups = 16-lane half-warps: shfl_xor 8..1)
        #pragma unroll
        for (int i = 0; i < 4; ++i) {
            float mx = fmaxf(fmaxf(s[i][0], s[i][1]), fmaxf(s[i][2], s[i][3]));
            #pragma unroll
            for (int o = 8; o >= 1; o >>= 1)
                mx = fmaxf(mx, __shfl_xor_sync(0xffffffffu, mx, o));
            float newm = fmaxf(m[i], mx);
            float f    = __expf(m[i] - newm);
            float psum = 0.0f;
            #pragma unroll
            for (int j = 0; j < 4; ++j) {
                float p = __expf(s[i][j] - newm);
                s[i][j] = p;
                psum += p;
            }
            #pragma unroll
            for (int o = 8; o >= 1; o >>= 1)
                psum += __shfl_xor_sync(0xffffffffu, psum, o);
            l[i] = l[i] * f + psum;
            m[i] = newm;
            #pragma unroll
            for (int j = 0; j < 4; ++j) acc[i][j] *= f;
            *(float4*)&Ps[ty * 4 + i][tx * 4] = *(float4*)&s[i][0];
        }
        __syncthreads();

        // O += P @ V
        #pragma unroll
        for (int k4 = 0; k4 < 16; ++k4) {
            float4 p4[4];
            #pragma unroll
            for (int i = 0; i < 4; ++i)
                p4[i] = *(const float4*)&Ps[ty * 4 + i][k4 * 4];
            #pragma unroll
            for (int kk = 0; kk < 4; ++kk) {
                float4 v4 = *(const float4*)&Vs[k4 * 4 + kk][tx * 4];
                #pragma unroll
                for (int i = 0; i < 4; ++i) {
                    float pv = ((const float*)&p4[i])[kk];
                    acc[i][0] = fmaf(pv, v4.x, acc[i][0]);
                    acc[i][1] = fmaf(pv, v4.y, acc[i][1]);
                    acc[i][2] = fmaf(pv, v4.z, acc[i][2]);
                    acc[i][3] = fmaf(pv, v4.w, acc[i][3]);
                }
            }
        }
    }

    // Epilogue: normalize, scatter to [B, S, EMB] for the output projection
    const int b = bh / H_, h = bh % H_;
    #pragma unroll
    for (int i = 0; i < 4; ++i) {
        float inv = 1.0f / l[i];
        int srow  = qt * AT + ty * 4 + i;
        float4 v;
        v.x = acc[i][0] * inv; v.y = acc[i][1] * inv;
        v.z = acc[i][2] * inv; v.w = acc[i][3] * inv;
        *(float4*)&g_attn[((size_t)b * S_ + srow) * EMB_ + h * HD_ + tx * 4] = v;
    }
}

// ---------------- launch ---------------------------------------------------
extern "C" void kernel_launch(void* const* d_in, const int* in_sizes, int n_in,
                              void* d_out, int out_size)
{
    const float* x  = (const float*)d_in[0];
    const float* Wq = (const float*)d_in[1];
    const float* bq = (const float*)d_in[2];
    const float* Wk = (const float*)d_in[3];
    const float* bk = (const float*)d_in[4];
    const float* Wv = (const float*)d_in[5];
    const float* bv = (const float*)d_in[6];
    const float* Wo = (const float*)d_in[7];
    const float* bo = (const float*)d_in[8];
    // d_in[9] = causal_mask (int32) — causality implemented analytically.
    float* out = (float*)d_out;

    cudaFuncSetAttribute(attn_kernel,
                         cudaFuncAttributeMaxDynamicSharedMemorySize, ATTN_SMEM);

    qkv_kernel<<<dim3(EMB_ / BN, M_ / BM, 3), 256>>>(x, Wq, bq, Wk, bk, Wv, bv);
    attn_kernel<<<dim3(S_ / AT, B_ * H_), 256, ATTN_SMEM>>>();
    oproj_kernel<<<dim3(EMB_ / BN, M_ / BM), 256>>>(Wo, bo, out);
}